// round 10
// baseline (speedup 1.0000x reference)
#include <cuda_runtime.h>
#include <cstdint>

// Problem shape
#define BB      16
#define TT      4096
#define UU      1024
#define TC      16                 // t-rows per chunk
#define RR      3                  // rows held in registers
#define SR      13                 // rows via cp.async into smem (column-private)
#define NC      (TT / TC)          // 256 chunks per batch chain
#define U4      (UU / 4)           // 256 float4 per row
#define THREADS 256                // one thread per float4 column
#define NTICK   (BB * NC)          // 4096 chunk tickets
#define GRID    304                // persistent: 2 blocks/SM x 152 SMs
#define FACTOR  0.5f
#define SMEM_BYTES (2 * SR * THREADS * 16)   // double-buffered tile: 104 KB

// Decoupled-lookback scratch (device globals: no allocation allowed).
// NOTE: flags/agg/inc are indexed by CHAIN ORDER fidx = b*NC + c  (NOT ticket
// order). R7 hung because publish used ticket index while polls used chain
// index. Tickets (vb: b = vb&15, c = vb>>4) only select the chunk to work on.
__device__ float4 g_agg[NTICK * U4];            // 16 MiB
__device__ float4 g_inc[NTICK * U4];            // 16 MiB
__device__ unsigned int g_flags[NTICK + 1];     // [fidx]; last = ticket counter

__device__ __forceinline__ void st_release_gpu(unsigned int* p, unsigned int v) {
    asm volatile("st.release.gpu.u32 [%0], %1;" :: "l"(p), "r"(v) : "memory");
}
__device__ __forceinline__ unsigned int ld_acquire_gpu(const unsigned int* p) {
    unsigned int v;
    asm volatile("ld.acquire.gpu.u32 %0, [%1];" : "=r"(v) : "l"(p) : "memory");
    return v;
}
__device__ __forceinline__ void cp_async16(uint32_t saddr, const void* gaddr) {
    asm volatile("cp.async.cg.shared.global [%0], [%1], 16;" :: "r"(saddr), "l"(gaddr));
}

__global__ __launch_bounds__(THREADS, 2)
void rac_scan_kernel(const float4* __restrict__ xv,
                     const float4* __restrict__ h0v,
                     float4* __restrict__ outv) {
    extern __shared__ float4 s_buf[];          // [2][SR*THREADS], column-private
    __shared__ unsigned int s_vb;
    __shared__ int s_D;
    __shared__ int s_done;

    const int tid = threadIdx.x;

    // ---- Prologue: take first ticket, issue its loads ----
    if (tid == 0) s_vb = atomicAdd(&g_flags[NTICK], 1u);
    __syncthreads();
    int cur = (int)s_vb;

    float4 vc[RR], vn[RR];
    size_t base_c = 0, base_n = 0;
    int w = 0;

    if (cur < NTICK) {
        const int b = cur & (BB - 1), c = cur >> 4;
        base_c = ((size_t)b * TT + (size_t)c * TC) * U4 + tid;
        const uint32_t sb = (uint32_t)__cvta_generic_to_shared(&s_buf[tid]);
#pragma unroll
        for (int t = 0; t < SR; t++)
            cp_async16(sb + t * (THREADS * 16),
                       (const void*)(xv + base_c + (size_t)(RR + t) * U4));
        asm volatile("cp.async.commit_group;" ::: "memory");
#pragma unroll
        for (int t = 0; t < RR; t++) vc[t] = xv[base_c + (size_t)t * U4];
    }

    while (cur < NTICK) {
        const int b = cur & (BB - 1);   // batch fastest -> all chains advance together
        const int c = cur >> 4;
        const int chain = b * NC;       // chain-order flag/scratch base
        const int fidx  = chain + c;    // THIS chunk's flag/scratch slot
        const int sidx  = fidx * U4 + tid;
        const bool is_last = (c == NC - 1);

        // ---- Take next ticket; issue its loads into the other buffer NOW. ----
        __syncthreads();                 // all threads done with prior s_vb/s_D
        if (tid == 0) s_vb = atomicAdd(&g_flags[NTICK], 1u);
        __syncthreads();
        const int nxt = (int)s_vb;
        const bool have_nxt = (nxt < NTICK);
        if (have_nxt) {
            const int nb = nxt & (BB - 1), nc = nxt >> 4;
            base_n = ((size_t)nb * TT + (size_t)nc * TC) * U4 + tid;
            const uint32_t sb = (uint32_t)__cvta_generic_to_shared(
                &s_buf[(w ^ 1) * (SR * THREADS) + tid]);
#pragma unroll
            for (int t = 0; t < SR; t++)
                cp_async16(sb + t * (THREADS * 16),
                           (const void*)(xv + base_n + (size_t)(RR + t) * U4));
            asm volatile("cp.async.commit_group;" ::: "memory");
#pragma unroll
            for (int t = 0; t < RR; t++) vn[t] = xv[base_n + (size_t)t * U4];
        }

        const float4 h = h0v[b * U4 + tid];

        // ---- Pre-phase lookback: overlapped with BOTH chunks' loads in flight.
        // Non-blocking: breaks as soon as a poll round shows no progress.
        float4 excl = make_float4(0.f, 0.f, 0.f, 0.f);
        int base_p = c - 1;
        bool done = (c == 0);
        while (!done) {
            if (tid < 32) {
                const int p = base_p - tid;
                const unsigned f = (p >= 0) ? ld_acquire_gpu(&g_flags[chain + p]) : 0u;
                const unsigned b1 = __ballot_sync(0xffffffffu, f >= 1u);
                const unsigned b2 = __ballot_sync(0xffffffffu, f == 2u);
                if (tid == 0) {
                    const int k = __ffs(~b1);             // first not-ready lane (+1)
                    const int nready = (k == 0) ? 32 : (k - 1);
                    const int l2 = __ffs(b2) - 1;         // nearest inclusive; -1 if none
                    if (l2 >= 0 && l2 <= nready) { s_done = 1; s_D = l2; }
                    else                         { s_done = 0; s_D = nready; }
                }
            }
            __syncthreads();
            const int D = s_D;
            const int fin = s_done;
            if (!fin && D == 0) break;   // no progress -> go consume our data
            for (int l = 0; l < D; l++) {
                const float4 a = __ldcg(&g_agg[(chain + base_p - l) * U4 + tid]);
                excl.x += a.x; excl.y += a.y; excl.z += a.z; excl.w += a.w;
            }
            if (fin) {
                const float4 a = __ldcg(&g_inc[(chain + base_p - D) * U4 + tid]);
                excl.x += a.x; excl.y += a.y; excl.z += a.z; excl.w += a.w;
                done = true;
                break;
            }
            base_p -= D;
            __syncthreads();             // protect s_D/s_done before next poll
        }

        // ---- Wait for cur's cp.async group only (nxt's keeps flying). ----
        if (have_nxt) asm volatile("cp.async.wait_group 1;" ::: "memory");
        else          asm volatile("cp.async.wait_group 0;" ::: "memory");

        // Local prefix: register rows then smem rows (column-private, no sync).
#pragma unroll
        for (int t = 1; t < RR; t++) {
            vc[t].x += vc[t - 1].x;
            vc[t].y += vc[t - 1].y;
            vc[t].z += vc[t - 1].z;
            vc[t].w += vc[t - 1].w;
        }
        float4* buf = &s_buf[w * (SR * THREADS)];
        float4 run = make_float4(0.f, 0.f, 0.f, 0.f);
#pragma unroll
        for (int t = 0; t < SR; t++) {
            const float4 a = buf[t * THREADS + tid];
            run.x += a.x; run.y += a.y; run.z += a.z; run.w += a.w;
            buf[t * THREADS + tid] = run;
        }
        float4 agg;
        agg.x = vc[RR - 1].x + run.x;
        agg.y = vc[RR - 1].y + run.y;
        agg.z = vc[RR - 1].z + run.z;
        agg.w = vc[RR - 1].w + run.w;

        if (done) {
            // Lookback resolved during loads: single publish, inclusive directly.
            if (!is_last) {
                float4 inc;
                inc.x = excl.x + agg.x; inc.y = excl.y + agg.y;
                inc.z = excl.z + agg.z; inc.w = excl.w + agg.w;
                g_inc[sidx] = inc;
                __syncthreads();         // all data stores happen-before the release
                if (tid == 0) st_release_gpu(&g_flags[fidx], 2u);
            }
        } else {
            // Publish aggregate so successors can make progress immediately.
            g_agg[sidx] = agg;
            __syncthreads();
            if (tid == 0) st_release_gpu(&g_flags[fidx], 1u);

            // Residual lookback (blocking) — nxt's loads still cover the stall.
            for (;;) {
                if (tid < 32) {
                    const int p = base_p - tid;
                    const unsigned f = (p >= 0) ? ld_acquire_gpu(&g_flags[chain + p]) : 0u;
                    const unsigned b1 = __ballot_sync(0xffffffffu, f >= 1u);
                    const unsigned b2 = __ballot_sync(0xffffffffu, f == 2u);
                    if (tid == 0) {
                        const int k = __ffs(~b1);
                        const int nready = (k == 0) ? 32 : (k - 1);
                        const int l2 = __ffs(b2) - 1;
                        if (l2 >= 0 && l2 <= nready) { s_done = 1; s_D = l2; }
                        else                         { s_done = 0; s_D = nready; }
                    }
                }
                __syncthreads();
                const int D = s_D;
                const int fin = s_done;
                for (int l = 0; l < D; l++) {
                    const float4 a = __ldcg(&g_agg[(chain + base_p - l) * U4 + tid]);
                    excl.x += a.x; excl.y += a.y; excl.z += a.z; excl.w += a.w;
                }
                if (fin) {
                    const float4 a = __ldcg(&g_inc[(chain + base_p - D) * U4 + tid]);
                    excl.x += a.x; excl.y += a.y; excl.z += a.z; excl.w += a.w;
                    break;
                }
                base_p -= D;
                __syncthreads();
            }

            // Upgrade to inclusive (flag 1 -> 2).
            if (!is_last) {
                float4 inc;
                inc.x = excl.x + agg.x; inc.y = excl.y + agg.y;
                inc.z = excl.z + agg.z; inc.w = excl.w + agg.w;
                g_inc[sidx] = inc;
                __syncthreads();
                if (tid == 0) st_release_gpu(&g_flags[fidx], 2u);
            }
        }

        // ---- Epilogue: out = h0 + FACTOR * (exclusive + local_prefix) ----
#pragma unroll
        for (int t = 0; t < RR; t++) {
            float4 o;
            o.x = h.x + FACTOR * (excl.x + vc[t].x);
            o.y = h.y + FACTOR * (excl.y + vc[t].y);
            o.z = h.z + FACTOR * (excl.z + vc[t].z);
            o.w = h.w + FACTOR * (excl.w + vc[t].w);
            outv[base_c + (size_t)t * U4] = o;
        }
        const float4 lo = vc[RR - 1];
#pragma unroll
        for (int t = 0; t < SR; t++) {
            const float4 p = buf[t * THREADS + tid];
            float4 o;
            o.x = h.x + FACTOR * (excl.x + lo.x + p.x);
            o.y = h.y + FACTOR * (excl.y + lo.y + p.y);
            o.z = h.z + FACTOR * (excl.z + lo.z + p.z);
            o.w = h.w + FACTOR * (excl.w + lo.w + p.w);
            outv[base_c + (size_t)(RR + t) * U4] = o;
        }

        // ---- Rotate pipeline state ----
        cur = nxt;
        base_c = base_n;
#pragma unroll
        for (int t = 0; t < RR; t++) vc[t] = vn[t];
        w ^= 1;
    }
}

extern "C" void kernel_launch(void* const* d_in, const int* in_sizes, int n_in,
                              void* d_out, int out_size) {
    (void)in_sizes; (void)n_in; (void)out_size;
    const float4* xv  = (const float4*)d_in[0];   // x:  (16, 4096, 1024) f32
    const float4* h0v = (const float4*)d_in[1];   // h0: (16, 1024) f32
    float4* outv      = (float4*)d_out;           // out:(16, 4096, 1024) f32

    // 104 KB dynamic smem needs an opt-in (host-side attribute; not an allocation).
    cudaFuncSetAttribute(rac_scan_kernel,
                         cudaFuncAttributeMaxDynamicSharedMemorySize, SMEM_BYTES);

    // Reset flags + ticket every launch (captured as a memset node).
    void* flags_ptr = nullptr;
    cudaGetSymbolAddress(&flags_ptr, g_flags);
    cudaMemsetAsync(flags_ptr, 0, (NTICK + 1) * sizeof(unsigned int), 0);

    rac_scan_kernel<<<GRID, THREADS, SMEM_BYTES>>>(xv, h0v, outv);
}

// round 11
// speedup vs baseline: 1.3553x; 1.3553x over previous
#include <cuda_runtime.h>
#include <cstdint>

// Problem shape
#define BB      16
#define TT      4096
#define UU      1024
#define TC      16                 // t-rows per chunk
#define RR      4                  // rows held in registers
#define SR      12                 // rows via cp.async into smem (column-private)
#define NC      (TT / TC)          // 256 chunks per batch chain
#define U4      (UU / 4)           // 256 float4 per row
#define THREADS 256                // one thread per float4 column
#define FACTOR  0.5f

// Decoupled-lookback scratch (device globals: no allocation allowed).
__device__ float4 g_agg[BB * NC * U4];          // 16 MiB
__device__ float4 g_inc[BB * NC * U4];          // 16 MiB
// Flags: 0 = invalid, 1 = aggregate ready, 2 = inclusive ready.
// Last slot doubles as the dynamic-ticket counter. Reset by memset each launch.
__device__ unsigned int g_flags[BB * NC + 1];

__device__ __forceinline__ void st_release_gpu(unsigned int* p, unsigned int v) {
    asm volatile("st.release.gpu.u32 [%0], %1;" :: "l"(p), "r"(v) : "memory");
}
__device__ __forceinline__ unsigned int ld_acquire_gpu(const unsigned int* p) {
    unsigned int v;
    asm volatile("ld.acquire.gpu.u32 %0, [%1];" : "=r"(v) : "l"(p) : "memory");
    return v;
}
__device__ __forceinline__ void cp_async16(uint32_t saddr, const void* gaddr) {
    asm volatile("cp.async.cg.shared.global [%0], [%1], 16;" :: "r"(saddr), "l"(gaddr));
}

__global__ __launch_bounds__(THREADS, 4)
void rac_scan_kernel(const float4* __restrict__ xv,
                     const float4* __restrict__ h0v,
                     float4* __restrict__ outv) {
    __shared__ float4 s_tile[SR * THREADS];   // 48 KB, column-private per thread
    __shared__ unsigned int s_vb;
    __shared__ int s_D;
    __shared__ int s_done;

    const int tid = threadIdx.x;

    // Dynamic ticket: chain order == scheduling order (no deadlock).
    if (tid == 0) s_vb = atomicAdd(&g_flags[BB * NC], 1u);
    __syncthreads();
    const unsigned int vb = s_vb;
    const int b = vb & (BB - 1);   // batch fastest -> all 16 chains advance together
    const int c = vb >> 4;         // chunk index along the chain

    const size_t base = ((size_t)b * TT + (size_t)c * TC) * U4 + tid;

    // Rows RR..TC-1 -> smem via cp.async (no register cost, deep MLP).
    const uint32_t sbase = (uint32_t)__cvta_generic_to_shared(&s_tile[tid]);
#pragma unroll
    for (int t = 0; t < SR; t++)
        cp_async16(sbase + t * (THREADS * 16),
                   (const void*)(xv + base + (size_t)(RR + t) * U4));
    asm volatile("cp.async.commit_group;" ::: "memory");

    const float4 h = h0v[b * U4 + tid];

    // Rows 0..RR-1 -> registers (streaming: x is read exactly once), prefixed.
    float4 v[RR];
#pragma unroll
    for (int t = 0; t < RR; t++) v[t] = __ldcs(&xv[base + (size_t)t * U4]);
#pragma unroll
    for (int t = 1; t < RR; t++) {
        v[t].x += v[t - 1].x;
        v[t].y += v[t - 1].y;
        v[t].z += v[t - 1].z;
        v[t].w += v[t - 1].w;
    }

    const int chain = b * NC;
    const int sidx  = (chain + c) * U4 + tid;
    const bool is_last = (c == NC - 1);
    float4 excl = make_float4(0.f, 0.f, 0.f, 0.f);

    // ---- Pre-phase lookback: overlapped with the cp.async flight. ----
    // Non-blocking: breaks as soon as a poll round shows no progress.
    int base_p = c - 1;
    bool done = (c == 0);
    while (!done) {
        if (tid < 32) {
            const int p = base_p - tid;
            const unsigned f = (p >= 0) ? ld_acquire_gpu(&g_flags[chain + p]) : 0u;
            const unsigned b1 = __ballot_sync(0xffffffffu, f >= 1u);
            const unsigned b2 = __ballot_sync(0xffffffffu, f == 2u);
            if (tid == 0) {
                const int k = __ffs(~b1);                 // first not-ready lane (+1)
                const int nready = (k == 0) ? 32 : (k - 1);
                const int l2 = __ffs(b2) - 1;             // nearest inclusive; -1 if none
                if (l2 >= 0 && l2 <= nready) { s_done = 1; s_D = l2; }
                else                         { s_done = 0; s_D = nready; }
            }
        }
        __syncthreads();
        const int D = s_D;
        const int fin = s_done;
        if (!fin && D == 0) break;       // no progress yet -> go back to our load
        for (int l = 0; l < D; l++) {
            const float4 a = __ldcg(&g_agg[(chain + base_p - l) * U4 + tid]);
            excl.x += a.x; excl.y += a.y; excl.z += a.z; excl.w += a.w;
        }
        if (fin) {
            const float4 a = __ldcg(&g_inc[(chain + base_p - D) * U4 + tid]);
            excl.x += a.x; excl.y += a.y; excl.z += a.z; excl.w += a.w;
            done = true;
            break;
        }
        base_p -= D;
        __syncthreads();                 // protect s_D/s_done before next poll
    }

    // ---- Wait for data; local prefix over smem rows (column-private, no sync). ----
    asm volatile("cp.async.wait_group 0;" ::: "memory");
    float4 run = make_float4(0.f, 0.f, 0.f, 0.f);
#pragma unroll
    for (int t = 0; t < SR; t++) {
        const float4 a = s_tile[t * THREADS + tid];
        run.x += a.x; run.y += a.y; run.z += a.z; run.w += a.w;
        s_tile[t * THREADS + tid] = run;
    }
    float4 agg;
    agg.x = v[RR - 1].x + run.x;
    agg.y = v[RR - 1].y + run.y;
    agg.z = v[RR - 1].z + run.z;
    agg.w = v[RR - 1].w + run.w;

    if (done) {
        // Lookback resolved during the load: single publish, inclusive directly.
        if (!is_last) {
            float4 inc;
            inc.x = excl.x + agg.x; inc.y = excl.y + agg.y;
            inc.z = excl.z + agg.z; inc.w = excl.w + agg.w;
            g_inc[sidx] = inc;
            __syncthreads();             // all data stores happen-before the release
            if (tid == 0) st_release_gpu(&g_flags[chain + c], 2u);
        }
    } else {
        // Publish aggregate so successors can make progress immediately.
        g_agg[sidx] = agg;
        __syncthreads();                 // HB for all threads' stores; also protects s_D
        if (tid == 0) st_release_gpu(&g_flags[chain + c], 1u);

        // ---- Residual lookback (blocking, same windowed protocol). ----
        for (;;) {
            if (tid < 32) {
                const int p = base_p - tid;
                const unsigned f = (p >= 0) ? ld_acquire_gpu(&g_flags[chain + p]) : 0u;
                const unsigned b1 = __ballot_sync(0xffffffffu, f >= 1u);
                const unsigned b2 = __ballot_sync(0xffffffffu, f == 2u);
                if (tid == 0) {
                    const int k = __ffs(~b1);
                    const int nready = (k == 0) ? 32 : (k - 1);
                    const int l2 = __ffs(b2) - 1;
                    if (l2 >= 0 && l2 <= nready) { s_done = 1; s_D = l2; }
                    else                         { s_done = 0; s_D = nready; }
                }
            }
            __syncthreads();
            const int D = s_D;
            const int fin = s_done;
            for (int l = 0; l < D; l++) {
                const float4 a = __ldcg(&g_agg[(chain + base_p - l) * U4 + tid]);
                excl.x += a.x; excl.y += a.y; excl.z += a.z; excl.w += a.w;
            }
            if (fin) {
                const float4 a = __ldcg(&g_inc[(chain + base_p - D) * U4 + tid]);
                excl.x += a.x; excl.y += a.y; excl.z += a.z; excl.w += a.w;
                break;
            }
            base_p -= D;
            __syncthreads();
        }

        // Upgrade to inclusive (flag 1 -> 2).
        if (!is_last) {
            float4 inc;
            inc.x = excl.x + agg.x; inc.y = excl.y + agg.y;
            inc.z = excl.z + agg.z; inc.w = excl.w + agg.w;
            g_inc[sidx] = inc;
            __syncthreads();
            if (tid == 0) st_release_gpu(&g_flags[chain + c], 2u);
        }
    }

    // ---- Epilogue: out = h0 + FACTOR * (exclusive + local_prefix) ----
    // __stcs: output is never re-read -> evict-first, keep L2 for the
    // lookback scratch (agg/inc/flags) instead of the write stream.
#pragma unroll
    for (int t = 0; t < RR; t++) {
        float4 o;
        o.x = h.x + FACTOR * (excl.x + v[t].x);
        o.y = h.y + FACTOR * (excl.y + v[t].y);
        o.z = h.z + FACTOR * (excl.z + v[t].z);
        o.w = h.w + FACTOR * (excl.w + v[t].w);
        __stcs(&outv[base + (size_t)t * U4], o);
    }
    const float4 lo = v[RR - 1];
#pragma unroll
    for (int t = 0; t < SR; t++) {
        const float4 p = s_tile[t * THREADS + tid];
        float4 o;
        o.x = h.x + FACTOR * (excl.x + lo.x + p.x);
        o.y = h.y + FACTOR * (excl.y + lo.y + p.y);
        o.z = h.z + FACTOR * (excl.z + lo.z + p.z);
        o.w = h.w + FACTOR * (excl.w + lo.w + p.w);
        __stcs(&outv[base + (size_t)(RR + t) * U4], o);
    }
}

extern "C" void kernel_launch(void* const* d_in, const int* in_sizes, int n_in,
                              void* d_out, int out_size) {
    (void)in_sizes; (void)n_in; (void)out_size;
    const float4* xv  = (const float4*)d_in[0];   // x:  (16, 4096, 1024) f32
    const float4* h0v = (const float4*)d_in[1];   // h0: (16, 1024) f32
    float4* outv      = (float4*)d_out;           // out:(16, 4096, 1024) f32

    // Reset flags + ticket every launch (captured as a memset node).
    void* flags_ptr = nullptr;
    cudaGetSymbolAddress(&flags_ptr, g_flags);
    cudaMemsetAsync(flags_ptr, 0, (BB * NC + 1) * sizeof(unsigned int), 0);

    rac_scan_kernel<<<BB * NC, THREADS>>>(xv, h0v, outv);
}